// round 5
// baseline (speedup 1.0000x reference)
#include <cuda_runtime.h>
#include <cuda_bf16.h>
#include <stdint.h>

#define HID 128
#define MAX_NODES 50000
#define MAX_EDGES 600000

// Scratch (allocation-free rule: __device__ globals)
__device__ float g_x[MAX_NODES * HID];       // gemm output per layer
__device__ float g_h0[MAX_NODES * HID];      // layer-0 hidden
__device__ float g_h1[MAX_NODES * HID];      // layer-1 hidden
__device__ int   g_cnt[MAX_NODES + 1];       // per-dst degree
__device__ int   g_off[MAX_NODES + 1];       // CSR row offsets
__device__ int   g_woff[MAX_NODES];          // scatter cursors
__device__ int2  g_es[MAX_EDGES];            // CSR payload: {edge_id, src}

// ---------------------------------------------------------------------------
// CSR build: zero counts -> histogram -> scan -> scatter
// ---------------------------------------------------------------------------
__global__ void zero_cnt_kernel(int* __restrict__ cnt, int n)
{
    int i = blockIdx.x * blockDim.x + threadIdx.x;
    if (i < n) cnt[i] = 0;
}

__global__ void hist_kernel(const int* __restrict__ ei, int* __restrict__ cnt, int E)
{
    int e = blockIdx.x * blockDim.x + threadIdx.x;
    if (e < E) atomicAdd(&cnt[ei[E + e]], 1);
}

// Single-block exclusive scan over N counts -> off (and woff copy), off[N]=E.
__global__ void __launch_bounds__(1024) scan_kernel(
    const int* __restrict__ cnt, int* __restrict__ off,
    int* __restrict__ woff, int N)
{
    __shared__ int sh[1024];
    int tid = threadIdx.x;
    int chunk = (N + 1023) / 1024;
    int start = tid * chunk;
    int end   = min(start + chunk, N);

    int s = 0;
    for (int i = start; i < end; i++) s += cnt[i];

    sh[tid] = s;
    __syncthreads();
    #pragma unroll
    for (int d = 1; d < 1024; d <<= 1) {
        int v = (tid >= d) ? sh[tid - d] : 0;
        __syncthreads();
        sh[tid] += v;
        __syncthreads();
    }
    int run = sh[tid] - s;   // exclusive prefix for this chunk

    for (int i = start; i < end; i++) {
        off[i]  = run;
        woff[i] = run;
        run += cnt[i];
    }
    if (end == N && start <= N) off[N] = run;
}

__global__ void scatter_kernel(const int* __restrict__ ei,
                               int* __restrict__ woff,
                               int2* __restrict__ es, int E)
{
    int e = blockIdx.x * blockDim.x + threadIdx.x;
    if (e >= E) return;
    int s = ei[e];
    int d = ei[E + e];
    int pos = atomicAdd(&woff[d], 1);
    es[pos] = make_int2(e, s);
}

// ---------------------------------------------------------------------------
// GEMM: out[M,128] = A[M,128] @ W[128,128], packed fma.rn.f32x2.
// 256 threads / 8 warps, W-only SMEM (64KB) -> 3 CTAs/SM. A is read directly
// from global: per (warp,row,k4) one broadcast LDG.128 (all lanes same addr).
// Warp w owns rows base+w*8..+7; lane owns cols lane*4..lane*4+3.
// ---------------------------------------------------------------------------
__global__ void __launch_bounds__(256, 3) gemm_kernel(
    const float* __restrict__ A, const float* __restrict__ W,
    float* __restrict__ out, int M)
{
    extern __shared__ float smem[];
    float* Wsh = smem;              // 128*128

    int tid  = threadIdx.x;
    int warp = tid >> 5;
    int lane = tid & 31;

    #pragma unroll
    for (int i = 0; i < 64; i++)
        Wsh[i * 256 + tid] = W[i * 256 + tid];
    __syncthreads();

    int row0 = blockIdx.x * 64 + warp * 8;

    unsigned long long acc2[8][2];
    #pragma unroll
    for (int j = 0; j < 8; j++) { acc2[j][0] = 0ULL; acc2[j][1] = 0ULL; }

    // guard: rows beyond M read row 0 (result discarded)
    const float* arow[8];
    #pragma unroll
    for (int j = 0; j < 8; j++)
        arow[j] = &A[(size_t)((row0 + j < M) ? row0 + j : 0) * HID];

    #pragma unroll 2
    for (int k = 0; k < HID; k += 4) {
        float4 a[8];
        #pragma unroll
        for (int j = 0; j < 8; j++)
            a[j] = __ldg((const float4*)(arow[j] + k));

        #pragma unroll
        for (int kk = 0; kk < 4; kk++) {
            ulonglong2 wv = *(const ulonglong2*)&Wsh[(k + kk) * HID + lane * 4];
            #pragma unroll
            for (int j = 0; j < 8; j++) {
                float av = (kk == 0) ? a[j].x : (kk == 1) ? a[j].y
                         : (kk == 2) ? a[j].z : a[j].w;
                unsigned long long ap;
                asm("mov.b64 %0, {%1, %1};" : "=l"(ap) : "f"(av));
                asm("fma.rn.f32x2 %0, %1, %2, %0;" : "+l"(acc2[j][0]) : "l"(ap), "l"(wv.x));
                asm("fma.rn.f32x2 %0, %1, %2, %0;" : "+l"(acc2[j][1]) : "l"(ap), "l"(wv.y));
            }
        }
    }

    #pragma unroll
    for (int j = 0; j < 8; j++) {
        int r = row0 + j;
        if (r < M) {
            float4 v;
            asm("mov.b64 {%0, %1}, %2;" : "=f"(v.x), "=f"(v.y) : "l"(acc2[j][0]));
            asm("mov.b64 {%0, %1}, %2;" : "=f"(v.z), "=f"(v.w) : "l"(acc2[j][1]));
            *(float4*)&out[(size_t)r * HID + lane * 4] = v;
        }
    }
}

// ---------------------------------------------------------------------------
// Fused gather: one warp per dst node, edge loop unrolled x4 with batched
// loads (MLP ~9) so DRAM/L2 latency is overlapped. x via __ldg (L1-cacheable,
// hub reuse); attr via __ldcs (stream, evict-first, protect L2-resident x).
// ---------------------------------------------------------------------------
__global__ void __launch_bounds__(256) gather_kernel(
    const float* __restrict__ x, const float* __restrict__ attr,
    const int* __restrict__ off, const int2* __restrict__ es,
    const float* __restrict__ bias, const float* __restrict__ cur,
    float* __restrict__ out, int N, int do_relu)
{
    int node = (blockIdx.x * (blockDim.x >> 5)) + (threadIdx.x >> 5);
    if (node >= N) return;
    int lane = threadIdx.x & 31;

    int o0  = off[node];
    int deg = off[node + 1] - o0;

    float a0 = 0.f, a1 = 0.f, a2 = 0.f, a3 = 0.f;

    int i = 0;
    for (; i + 4 <= deg; i += 4) {
        int2 e0 = es[o0 + i + 0];
        int2 e1 = es[o0 + i + 1];
        int2 e2 = es[o0 + i + 2];
        int2 e3 = es[o0 + i + 3];

        float4 x0 = __ldg((const float4*)&x[(size_t)e0.y * HID + lane * 4]);
        float4 x1 = __ldg((const float4*)&x[(size_t)e1.y * HID + lane * 4]);
        float4 x2 = __ldg((const float4*)&x[(size_t)e2.y * HID + lane * 4]);
        float4 x3 = __ldg((const float4*)&x[(size_t)e3.y * HID + lane * 4]);
        float4 v0 = __ldcs((const float4*)&attr[(size_t)e0.x * HID + lane * 4]);
        float4 v1 = __ldcs((const float4*)&attr[(size_t)e1.x * HID + lane * 4]);
        float4 v2 = __ldcs((const float4*)&attr[(size_t)e2.x * HID + lane * 4]);
        float4 v3 = __ldcs((const float4*)&attr[(size_t)e3.x * HID + lane * 4]);

        a0 += fmaxf(x0.x + v0.x, 0.f) + fmaxf(x1.x + v1.x, 0.f)
            + fmaxf(x2.x + v2.x, 0.f) + fmaxf(x3.x + v3.x, 0.f);
        a1 += fmaxf(x0.y + v0.y, 0.f) + fmaxf(x1.y + v1.y, 0.f)
            + fmaxf(x2.y + v2.y, 0.f) + fmaxf(x3.y + v3.y, 0.f);
        a2 += fmaxf(x0.z + v0.z, 0.f) + fmaxf(x1.z + v1.z, 0.f)
            + fmaxf(x2.z + v2.z, 0.f) + fmaxf(x3.z + v3.z, 0.f);
        a3 += fmaxf(x0.w + v0.w, 0.f) + fmaxf(x1.w + v1.w, 0.f)
            + fmaxf(x2.w + v2.w, 0.f) + fmaxf(x3.w + v3.w, 0.f);
    }
    for (; i < deg; i++) {
        int2 e = es[o0 + i];
        float4 xv = __ldg((const float4*)&x[(size_t)e.y * HID + lane * 4]);
        float4 av = __ldcs((const float4*)&attr[(size_t)e.x * HID + lane * 4]);
        a0 += fmaxf(xv.x + av.x, 0.f);
        a1 += fmaxf(xv.y + av.y, 0.f);
        a2 += fmaxf(xv.z + av.z, 0.f);
        a3 += fmaxf(xv.w + av.w, 0.f);
    }

    const float4 b4 = *(const float4*)&bias[lane * 4];
    float v0 = a0 + b4.x, v1 = a1 + b4.y, v2 = a2 + b4.z, v3 = a3 + b4.w;
    if (do_relu) {
        v0 = fmaxf(v0, 0.f); v1 = fmaxf(v1, 0.f);
        v2 = fmaxf(v2, 0.f); v3 = fmaxf(v3, 0.f);
    }
    const float4 c4 = *(const float4*)&cur[(size_t)node * HID + lane * 4];
    *(float4*)&out[(size_t)node * HID + lane * 4] =
        make_float4(v0 + c4.x, v1 + c4.y, v2 + c4.z, v3 + c4.w);
}

// ---------------------------------------------------------------------------
// Host launcher
// ---------------------------------------------------------------------------
extern "C" void kernel_launch(void* const* d_in, const int* in_sizes, int n_in,
                              void* d_out, int out_size)
{
    const float* z    = (const float*)d_in[0];
    const int*   ei   = (const int*)d_in[1];     // int32 (jax x64 disabled)
    const float* attr = (const float*)d_in[2];
    const float* W    = (const float*)d_in[3];
    const float* b    = (const float*)d_in[4];
    float*       out  = (float*)d_out;

    const int N = in_sizes[0] / HID;       // 50000
    const int E = in_sizes[1] / 2;         // 600000

    float *x, *h0, *h1;
    int *cnt, *off, *woff;
    int2 *es;
    cudaGetSymbolAddress((void**)&x,    g_x);
    cudaGetSymbolAddress((void**)&h0,   g_h0);
    cudaGetSymbolAddress((void**)&h1,   g_h1);
    cudaGetSymbolAddress((void**)&cnt,  g_cnt);
    cudaGetSymbolAddress((void**)&off,  g_off);
    cudaGetSymbolAddress((void**)&woff, g_woff);
    cudaGetSymbolAddress((void**)&es,   g_es);

    const int gemm_smem = HID * HID * sizeof(float);
    cudaFuncSetAttribute(gemm_kernel,
                         cudaFuncAttributeMaxDynamicSharedMemorySize,
                         gemm_smem);

    // CSR build (per replay; edge_index is an input)
    zero_cnt_kernel<<<(N + 256) / 256, 256>>>(cnt, N + 1);
    hist_kernel<<<(E + 255) / 256, 256>>>(ei, cnt, E);
    scan_kernel<<<1, 1024>>>(cnt, off, woff, N);
    scatter_kernel<<<(E + 255) / 256, 256>>>(ei, woff, es, E);

    const int gemm_grid   = (N + 63) / 64;
    const int gather_grid = (N + 7) / 8;    // 8 warps/block, 1 warp/node

    const float* cur = z;
    float* layer_out[3] = { h0, h1, out };

    for (int i = 0; i < 3; i++) {
        gemm_kernel<<<gemm_grid, 256, gemm_smem>>>(cur, W + i * HID * HID, x, N);
        gather_kernel<<<gather_grid, 256>>>(x, attr, off, es,
                                            b + i * HID, cur, layer_out[i],
                                            N, (i < 2) ? 1 : 0);
        cur = layer_out[i];
    }
}

// round 6
// speedup vs baseline: 1.0870x; 1.0870x over previous
#include <cuda_runtime.h>
#include <cuda_bf16.h>
#include <stdint.h>

#define HID 128
#define MAX_NODES 50000
#define MAX_EDGES 600000

// Scratch (allocation-free rule: __device__ globals)
__device__ float g_x[MAX_NODES * HID];       // gemm output per layer
__device__ float g_h0[MAX_NODES * HID];      // layer-0 hidden
__device__ float g_h1[MAX_NODES * HID];      // layer-1 hidden
__device__ int   g_cnt[MAX_NODES + 1];       // per-dst degree
__device__ int   g_off[MAX_NODES + 1];       // CSR row offsets
__device__ int   g_woff[MAX_NODES];          // scatter cursors
__device__ int2  g_es[MAX_EDGES];            // CSR payload: {edge_id, src}

// ---------------------------------------------------------------------------
// CSR build: zero counts -> histogram -> scan -> scatter
// ---------------------------------------------------------------------------
__global__ void zero_cnt_kernel(int* __restrict__ cnt, int n)
{
    int i = blockIdx.x * blockDim.x + threadIdx.x;
    if (i < n) cnt[i] = 0;
}

__global__ void hist_kernel(const int* __restrict__ ei, int* __restrict__ cnt, int E)
{
    int e = blockIdx.x * blockDim.x + threadIdx.x;
    if (e < E) atomicAdd(&cnt[ei[E + e]], 1);
}

// Single-block exclusive scan over N counts -> off (and woff copy), off[N]=E.
__global__ void __launch_bounds__(1024) scan_kernel(
    const int* __restrict__ cnt, int* __restrict__ off,
    int* __restrict__ woff, int N)
{
    __shared__ int sh[1024];
    int tid = threadIdx.x;
    int chunk = (N + 1023) / 1024;
    int start = tid * chunk;
    int end   = min(start + chunk, N);

    int s = 0;
    for (int i = start; i < end; i++) s += cnt[i];

    sh[tid] = s;
    __syncthreads();
    #pragma unroll
    for (int d = 1; d < 1024; d <<= 1) {
        int v = (tid >= d) ? sh[tid - d] : 0;
        __syncthreads();
        sh[tid] += v;
        __syncthreads();
    }
    int run = sh[tid] - s;   // exclusive prefix for this chunk

    for (int i = start; i < end; i++) {
        off[i]  = run;
        woff[i] = run;
        run += cnt[i];
    }
    if (end == N && start <= N) off[N] = run;
}

__global__ void scatter_kernel(const int* __restrict__ ei,
                               int* __restrict__ woff,
                               int2* __restrict__ es, int E)
{
    int e = blockIdx.x * blockDim.x + threadIdx.x;
    if (e >= E) return;
    int s = ei[e];
    int d = ei[E + e];
    int pos = atomicAdd(&woff[d], 1);
    es[pos] = make_int2(e, s);
}

// ---------------------------------------------------------------------------
// GEMM (R3 staged version — known good): out[M,128] = A[M,128] @ W[128,128]
// packed fma.rn.f32x2. 256 threads / 8 warps. W in SMEM (64KB) + 64 staged
// A rows (32KB). Warp w owns rows w*8..w*8+7; lane owns cols lane*4..+3.
// ---------------------------------------------------------------------------
__global__ void __launch_bounds__(256, 2) gemm_kernel(
    const float* __restrict__ A, const float* __restrict__ W,
    float* __restrict__ out, int M)
{
    extern __shared__ float smem[];
    float* Wsh = smem;              // 128*128
    float* Ash = smem + HID * HID;  // 64*128

    int tid  = threadIdx.x;
    int warp = tid >> 5;
    int lane = tid & 31;

    #pragma unroll
    for (int i = 0; i < 64; i++)
        Wsh[i * 256 + tid] = W[i * 256 + tid];

    int base = blockIdx.x * 64;
    for (int i = tid; i < 64 * HID; i += 256) {
        int r = base + (i >> 7);
        Ash[i] = (r < M) ? A[r * HID + (i & 127)] : 0.0f;
    }
    __syncthreads();

    unsigned long long acc2[8][2];
    #pragma unroll
    for (int j = 0; j < 8; j++) { acc2[j][0] = 0ULL; acc2[j][1] = 0ULL; }

    const float* arow = &Ash[(warp * 8) * HID];

    #pragma unroll 4
    for (int k = 0; k < HID; k++) {
        ulonglong2 wv = *(const ulonglong2*)&Wsh[k * HID + lane * 4];
        #pragma unroll
        for (int j = 0; j < 8; j++) {
            float a = arow[j * HID + k];
            unsigned long long ap;
            asm("mov.b64 %0, {%1, %1};" : "=l"(ap) : "f"(a));
            asm("fma.rn.f32x2 %0, %1, %2, %0;" : "+l"(acc2[j][0]) : "l"(ap), "l"(wv.x));
            asm("fma.rn.f32x2 %0, %1, %2, %0;" : "+l"(acc2[j][1]) : "l"(ap), "l"(wv.y));
        }
    }

    #pragma unroll
    for (int j = 0; j < 8; j++) {
        int r = base + warp * 8 + j;
        if (r < M) {
            float4 v;
            asm("mov.b64 {%0, %1}, %2;" : "=f"(v.x), "=f"(v.y) : "l"(acc2[j][0]));
            asm("mov.b64 {%0, %1}, %2;" : "=f"(v.z), "=f"(v.w) : "l"(acc2[j][1]));
            *(float4*)&out[(size_t)r * HID + lane * 4] = v;
        }
    }
}

// ---------------------------------------------------------------------------
// Fused gather (R4 version): one warp per dst node, edge loop unrolled x4
// with batched loads (MLP ~9). x via __ldg; attr via __ldcs (stream).
// ---------------------------------------------------------------------------
__global__ void __launch_bounds__(256) gather_kernel(
    const float* __restrict__ x, const float* __restrict__ attr,
    const int* __restrict__ off, const int2* __restrict__ es,
    const float* __restrict__ bias, const float* __restrict__ cur,
    float* __restrict__ out, int N, int do_relu)
{
    int node = (blockIdx.x * (blockDim.x >> 5)) + (threadIdx.x >> 5);
    if (node >= N) return;
    int lane = threadIdx.x & 31;

    int o0  = off[node];
    int deg = off[node + 1] - o0;

    float a0 = 0.f, a1 = 0.f, a2 = 0.f, a3 = 0.f;

    int i = 0;
    for (; i + 4 <= deg; i += 4) {
        int2 e0 = es[o0 + i + 0];
        int2 e1 = es[o0 + i + 1];
        int2 e2 = es[o0 + i + 2];
        int2 e3 = es[o0 + i + 3];

        float4 x0 = __ldg((const float4*)&x[(size_t)e0.y * HID + lane * 4]);
        float4 x1 = __ldg((const float4*)&x[(size_t)e1.y * HID + lane * 4]);
        float4 x2 = __ldg((const float4*)&x[(size_t)e2.y * HID + lane * 4]);
        float4 x3 = __ldg((const float4*)&x[(size_t)e3.y * HID + lane * 4]);
        float4 v0 = __ldcs((const float4*)&attr[(size_t)e0.x * HID + lane * 4]);
        float4 v1 = __ldcs((const float4*)&attr[(size_t)e1.x * HID + lane * 4]);
        float4 v2 = __ldcs((const float4*)&attr[(size_t)e2.x * HID + lane * 4]);
        float4 v3 = __ldcs((const float4*)&attr[(size_t)e3.x * HID + lane * 4]);

        a0 += fmaxf(x0.x + v0.x, 0.f) + fmaxf(x1.x + v1.x, 0.f)
            + fmaxf(x2.x + v2.x, 0.f) + fmaxf(x3.x + v3.x, 0.f);
        a1 += fmaxf(x0.y + v0.y, 0.f) + fmaxf(x1.y + v1.y, 0.f)
            + fmaxf(x2.y + v2.y, 0.f) + fmaxf(x3.y + v3.y, 0.f);
        a2 += fmaxf(x0.z + v0.z, 0.f) + fmaxf(x1.z + v1.z, 0.f)
            + fmaxf(x2.z + v2.z, 0.f) + fmaxf(x3.z + v3.z, 0.f);
        a3 += fmaxf(x0.w + v0.w, 0.f) + fmaxf(x1.w + v1.w, 0.f)
            + fmaxf(x2.w + v2.w, 0.f) + fmaxf(x3.w + v3.w, 0.f);
    }
    for (; i < deg; i++) {
        int2 e = es[o0 + i];
        float4 xv = __ldg((const float4*)&x[(size_t)e.y * HID + lane * 4]);
        float4 av = __ldcs((const float4*)&attr[(size_t)e.x * HID + lane * 4]);
        a0 += fmaxf(xv.x + av.x, 0.f);
        a1 += fmaxf(xv.y + av.y, 0.f);
        a2 += fmaxf(xv.z + av.z, 0.f);
        a3 += fmaxf(xv.w + av.w, 0.f);
    }

    const float4 b4 = *(const float4*)&bias[lane * 4];
    float v0 = a0 + b4.x, v1 = a1 + b4.y, v2 = a2 + b4.z, v3 = a3 + b4.w;
    if (do_relu) {
        v0 = fmaxf(v0, 0.f); v1 = fmaxf(v1, 0.f);
        v2 = fmaxf(v2, 0.f); v3 = fmaxf(v3, 0.f);
    }
    const float4 c4 = *(const float4*)&cur[(size_t)node * HID + lane * 4];
    *(float4*)&out[(size_t)node * HID + lane * 4] =
        make_float4(v0 + c4.x, v1 + c4.y, v2 + c4.z, v3 + c4.w);
}

// ---------------------------------------------------------------------------
// Host launcher
// ---------------------------------------------------------------------------
extern "C" void kernel_launch(void* const* d_in, const int* in_sizes, int n_in,
                              void* d_out, int out_size)
{
    const float* z    = (const float*)d_in[0];
    const int*   ei   = (const int*)d_in[1];     // int32 (jax x64 disabled)
    const float* attr = (const float*)d_in[2];
    const float* W    = (const float*)d_in[3];
    const float* b    = (const float*)d_in[4];
    float*       out  = (float*)d_out;

    const int N = in_sizes[0] / HID;       // 50000
    const int E = in_sizes[1] / 2;         // 600000

    float *x, *h0, *h1;
    int *cnt, *off, *woff;
    int2 *es;
    cudaGetSymbolAddress((void**)&x,    g_x);
    cudaGetSymbolAddress((void**)&h0,   g_h0);
    cudaGetSymbolAddress((void**)&h1,   g_h1);
    cudaGetSymbolAddress((void**)&cnt,  g_cnt);
    cudaGetSymbolAddress((void**)&off,  g_off);
    cudaGetSymbolAddress((void**)&woff, g_woff);
    cudaGetSymbolAddress((void**)&es,   g_es);

    const int gemm_smem = (HID * HID + 64 * HID) * sizeof(float);
    cudaFuncSetAttribute(gemm_kernel,
                         cudaFuncAttributeMaxDynamicSharedMemorySize,
                         gemm_smem);

    // CSR build (per replay; edge_index is an input)
    zero_cnt_kernel<<<(N + 256) / 256, 256>>>(cnt, N + 1);
    hist_kernel<<<(E + 255) / 256, 256>>>(ei, cnt, E);
    scan_kernel<<<1, 1024>>>(cnt, off, woff, N);
    scatter_kernel<<<(E + 255) / 256, 256>>>(ei, woff, es, E);

    const int gemm_grid   = (N + 63) / 64;
    const int gather_grid = (N + 7) / 8;    // 8 warps/block, 1 warp/node

    const float* cur = z;
    float* layer_out[3] = { h0, h1, out };

    for (int i = 0; i < 3; i++) {
        gemm_kernel<<<gemm_grid, 256, gemm_smem>>>(cur, W + i * HID * HID, x, N);
        gather_kernel<<<gather_grid, 256>>>(x, attr, off, es,
                                            b + i * HID, cur, layer_out[i],
                                            N, (i < 2) ? 1 : 0);
        cur = layer_out[i];
    }
}